// round 9
// baseline (speedup 1.0000x reference)
#include <cuda_runtime.h>

#define BB 2
#define L 384
#define D 256
#define H 8
#define DH 32
#define BL (BB*L)
#define INVS 0.17677669529663687f   // 1/sqrt(32)

// ---------------- scratch (static device globals; no allocations) ----------------
__device__ float g_kproj[BB*H*L*DH];   // [b][h][l][dh]
__device__ float g_qu[BB*H*L*DH];      // (q+u)*INVS, [b][h][l][dh]
__device__ float g_vproj[BB*H*L*DH];   // [b][h][l][dh]
__device__ float g_vT[BB*H*DH*L];      // V transposed: [z][dh][k]
__device__ float g_qlin[BL*D];         // raw q projection [m][d]
__device__ float g_w[BL*H*D];          // folded pos-weights [m][h][d], pre-scaled
__device__ float g_bias[BB*H*L];       // B_D bias term, pre-scaled
__device__ float g_score[BB*H*L*L];    // A_C+bias+mask, then attn  [z][q][k]

// ---------------- helpers ----------------
__device__ __forceinline__ void fma2(unsigned long long& acc, unsigned long long a, unsigned long long b) {
    asm("fma.rn.f32x2 %0, %1, %2, %0;" : "+l"(acc) : "l"(a), "l"(b));
}
__device__ __forceinline__ float hsum2(unsigned long long v) {
    return __uint_as_float((unsigned)v) + __uint_as_float((unsigned)(v >> 32));
}
__device__ __forceinline__ void cp16(unsigned saddr, const void* gptr) {
    asm volatile("cp.async.cg.shared.global [%0], [%1], 16;" :: "r"(saddr), "l"(gptr));
}

// ---------------- 1) QKV projections (transposed smem, scalar acc) ----------------
__global__ __launch_bounds__(256) void proj_kernel(
    const float* __restrict__ key, const float* __restrict__ query, const float* __restrict__ value,
    const float* __restrict__ Wk, const float* __restrict__ bk,
    const float* __restrict__ Wq, const float* __restrict__ bq,
    const float* __restrict__ Wv, const float* __restrict__ bv,
    const float* __restrict__ u)
{
    int op = blockIdx.z;
    const float* X = (op == 0) ? key : (op == 1) ? query : value;
    const float* W = (op == 0) ? Wk  : (op == 1) ? Wq    : Wv;
    const float* bs = (op == 0) ? bk : (op == 1) ? bq    : bv;
    int m0 = blockIdx.x * 64, n0 = blockIdx.y * 64;
    __shared__ float xsT[32][68], wsT[32][68];   // transposed [k][row]
    int t = threadIdx.x, tx = t & 15, ty = t >> 4;
    float c[4][4] = {};
    for (int k0 = 0; k0 < D; k0 += 32) {
        __syncthreads();
        for (int f = t; f < 512; f += 256) {
            int row = f >> 3, c4 = (f & 7) * 4;
            float4 xv = *(const float4*)&X[(m0 + row)*D + k0 + c4];
            float4 wv = *(const float4*)&W[(n0 + row)*D + k0 + c4];
            xsT[c4+0][row] = xv.x; xsT[c4+1][row] = xv.y;
            xsT[c4+2][row] = xv.z; xsT[c4+3][row] = xv.w;
            wsT[c4+0][row] = wv.x; wsT[c4+1][row] = wv.y;
            wsT[c4+2][row] = wv.z; wsT[c4+3][row] = wv.w;
        }
        __syncthreads();
        #pragma unroll
        for (int kk = 0; kk < 32; kk++) {
            float4 a4 = *(const float4*)&xsT[kk][ty*4];
            float4 b4 = *(const float4*)&wsT[kk][tx*4];
            float ar[4] = {a4.x, a4.y, a4.z, a4.w};
            #pragma unroll
            for (int i = 0; i < 4; i++) {
                c[i][0] += ar[i]*b4.x; c[i][1] += ar[i]*b4.y;
                c[i][2] += ar[i]*b4.z; c[i][3] += ar[i]*b4.w;
            }
        }
    }
    int n = n0 + tx*4;                 // 4-aligned; h,dh constant over the float4
    int h = n >> 5, dh = n & 31;
    float4 bs4 = *(const float4*)&bs[n];
    #pragma unroll
    for (int i = 0; i < 4; i++) {
        int m = m0 + ty*4 + i, b = m / L, l = m % L;
        float4 o = {c[i][0]+bs4.x, c[i][1]+bs4.y, c[i][2]+bs4.z, c[i][3]+bs4.w};
        int idx = ((b*H + h)*L + l)*DH + dh;
        if (op == 0)      *(float4*)&g_kproj[idx] = o;
        else if (op == 2) *(float4*)&g_vproj[idx] = o;
        else {
            *(float4*)&g_qlin[m*D + n] = o;
            float4 u4 = *(const float4*)&u[n];
            float4 q = {(o.x+u4.x)*INVS, (o.y+u4.y)*INVS, (o.z+u4.z)*INVS, (o.w+u4.w)*INVS};
            *(float4*)&g_qu[idx] = q;
        }
    }
}

// ---------------- 2) fused setup: ac | w | bias ----------------
__global__ __launch_bounds__(256) void setup_kernel(
    const float* __restrict__ key_mask,
    const float* __restrict__ Wr, const float* __restrict__ vpar,
    const float* __restrict__ br)
{
    __shared__ float sh0[32][68], sh1[32][68];
    int bz = blockIdx.x;
    int t = threadIdx.x, tx = t & 15, ty = t >> 4;

    if (bz < 576) {
        // ---- content scores A_C (+bias +mask) ----
        int idx = bz;
        int z = idx & 15;                 // b*H + h
        int rr = idx >> 4;
        int q0 = (rr % 6) * 64, k0 = (rr / 6) * 64;
        int b = z >> 3;
        for (int f = t; f < 512; f += 256) {
            int row = f >> 3, c4 = (f & 7) * 4;
            float4 qv = *(const float4*)&g_qu[(z*L + q0 + row)*DH + c4];
            float4 kv = *(const float4*)&g_kproj[(z*L + k0 + row)*DH + c4];
            sh0[c4+0][row] = qv.x; sh0[c4+1][row] = qv.y;
            sh0[c4+2][row] = qv.z; sh0[c4+3][row] = qv.w;
            sh1[c4+0][row] = kv.x; sh1[c4+1][row] = kv.y;
            sh1[c4+2][row] = kv.z; sh1[c4+3][row] = kv.w;
        }
        __syncthreads();
        float c[4][4] = {};
        #pragma unroll
        for (int kk = 0; kk < 32; kk++) {
            float4 a4 = *(const float4*)&sh0[kk][ty*4];
            float4 b4 = *(const float4*)&sh1[kk][tx*4];
            float ar[4] = {a4.x, a4.y, a4.z, a4.w};
            #pragma unroll
            for (int i = 0; i < 4; i++) {
                c[i][0] += ar[i]*b4.x; c[i][1] += ar[i]*b4.y;
                c[i][2] += ar[i]*b4.z; c[i][3] += ar[i]*b4.w;
            }
        }
        float msk[4];
        #pragma unroll
        for (int j = 0; j < 4; j++)
            msk[j] = (1.f - key_mask[b*L + k0 + tx*4 + j]) * 1e15f;
        #pragma unroll
        for (int i = 0; i < 4; i++) {
            int q = q0 + ty*4 + i;
            float bias = g_bias[z*L + q];
            float4 o;
            o.x = c[i][0] + bias - msk[0];
            o.y = c[i][1] + bias - msk[1];
            o.z = c[i][2] + bias - msk[2];
            o.w = c[i][3] + bias - msk[3];
            *(float4*)&g_score[((size_t)z*L + q)*L + k0 + tx*4] = o;
        }
    } else if (bz < 960) {
        // ---- w fold: per head h, [768,32] @ Wr_h[32,256] ----
        int idx = bz - 576;
        int h = idx & 7;
        int rr = idx >> 3;
        int m0 = (rr % 12) * 64, n0 = (rr / 12) * 64;
        for (int f = t; f < 512; f += 256) {
            int row = f >> 3, c4 = (f & 7) * 4;
            float4 qv = *(const float4*)&g_qlin[(m0 + row)*D + h*DH + c4];
            float4 vv = *(const float4*)&vpar[h*DH + c4];
            sh0[c4+0][row] = qv.x + vv.x;
            sh0[c4+1][row] = qv.y + vv.y;
            sh0[c4+2][row] = qv.z + vv.z;
            sh0[c4+3][row] = qv.w + vv.w;
        }
        for (int f = t; f < 512; f += 256) {
            int row = f >> 4, c4 = (f & 15) * 4;
            *(float4*)&sh1[row][c4] = *(const float4*)&Wr[(h*DH + row)*D + n0 + c4];
        }
        __syncthreads();
        float c[4][4] = {};
        #pragma unroll
        for (int jj = 0; jj < 32; jj++) {
            float4 a4 = *(const float4*)&sh0[jj][ty*4];
            float4 w4 = *(const float4*)&sh1[jj][tx*4];
            float ar[4] = {a4.x, a4.y, a4.z, a4.w};
            #pragma unroll
            for (int i = 0; i < 4; i++) {
                c[i][0] += ar[i]*w4.x; c[i][1] += ar[i]*w4.y;
                c[i][2] += ar[i]*w4.z; c[i][3] += ar[i]*w4.w;
            }
        }
        #pragma unroll
        for (int i = 0; i < 4; i++) {
            int m = m0 + ty*4 + i;
            float4 o = {c[i][0]*INVS, c[i][1]*INVS, c[i][2]*INVS, c[i][3]*INVS};
            *(float4*)&g_w[(m*H + h)*D + n0 + tx*4] = o;
        }
    } else {
        // ---- B_D bias ----
        int idx = (bz - 960) * 256 + t;
        int m = idx >> 3, h = idx & 7;
        float s = 0.f;
        for (int j = 0; j < DH; j++)
            s += (g_qlin[m*D + h*DH + j] + vpar[h*DH + j]) * br[h*DH + j];
        int b = m / L, l = m % L;
        g_bias[(b*H + h)*L + l] = s * INVS;
    }
}

// ---------------- 2b) V transpose (standalone: keeps bd in profiled launch slot 3) ----------------
__global__ __launch_bounds__(256) void vt_kernel() {
    int z = blockIdx.x;   // 0..15
    for (int f = threadIdx.x; f < L*DH; f += 256) {
        int k = f >> 5, d = f & 31;
        g_vT[((size_t)z*DH + d)*L + k] = g_vproj[((size_t)z*L + k)*DH + d];
    }
}

// ---------------- 3) MAIN: 768 threads, depth-2 cp.async pipeline, B_D + softmax ----------------
#define DCHUNK 32
#define PSTR 36          // 32 + 4 pad: conflict-free LDS.128 (8-lane phases hit distinct banks)
#define NCHUNK 8         // D / DCHUNK
#define MPB 6            // m's per block; 128 * 6 = 768
#define NG (MPB*NCHUNK)  // 48 chunks per CTA
#define BDT 768          // threads: 2 halves x 384 keys
extern __shared__ float smem3[];
__global__ __launch_bounds__(BDT, 1) void bd_softmax_kernel(const float* __restrict__ pos) {
    float* w_s  = smem3;                       // 2048 floats
    float* buf0 = smem3 + 2048;                // 3 x 384*36 floats
    float* bufs[3] = { buf0, buf0 + 384*PSTR, buf0 + 2*384*PSTR };
    __shared__ float red[16];
    int t = threadIdx.x;
    int half = t / 384;          // 0 or 1: which 16-dim half of each chunk
    int key  = t - half*384;     // 0..383
    int m0 = blockIdx.x * MPB;
    unsigned sbuf[3];
    #pragma unroll
    for (int j = 0; j < 3; j++) sbuf[j] = (unsigned)__cvta_generic_to_shared(bufs[j]);
    int rowb = t >> 3, c8 = (t & 7) << 2;      // cp.async slot: 4 float4 per thread

    // prologue: prefetch chunks g=0,1 into bufs 0,1 (separate groups)
    #pragma unroll
    for (int g = 0; g < 2; g++) {
        const float* src = pos + (size_t)m0*(L*D) + g*DCHUNK;
        #pragma unroll
        for (int k = 0; k < 4; k++) {
            int row = rowb + k*96;
            cp16(sbuf[g] + (unsigned)(row*PSTR + c8)*4u, src + row*D + c8);
        }
        asm volatile("cp.async.commit_group;");
    }

    for (int i = 0; i < MPB; i++) {
        int m = m0 + i;
        // w for this m (float4) + score row prefetch (half 0 only)
        for (int j = t; j < 512; j += BDT)
            *(float4*)&w_s[j*4] = *(const float4*)&g_w[(size_t)m*(H*D) + j*4];
        int bq = m / L, q = m - bq*L;
        float sc0[8];
        if (half == 0) {
            #pragma unroll
            for (int h = 0; h < 8; h++)
                sc0[h] = g_score[((size_t)(bq*H + h)*L + q)*L + key];
        }

        unsigned long long acc[8] = {};
        for (int c = 0; c < NCHUNK; c++) {
            int g = i*NCHUNK + c;
            // prefetch chunk g+2 (one commit every iteration keeps group ring aligned)
            int gp = g + 2;
            if (gp < NG) {
                int mi = gp >> 3, cc = gp & 7;
                const float* src = pos + (size_t)(m0 + mi)*(L*D) + cc*DCHUNK;
                unsigned sb = sbuf[gp % 3];
                #pragma unroll
                for (int k = 0; k < 4; k++) {
                    int row = rowb + k*96;
                    cp16(sb + (unsigned)(row*PSTR + c8)*4u, src + row*D + c8);
                }
            }
            asm volatile("cp.async.commit_group;");
            asm volatile("cp.async.wait_group 2;");   // chunk g's group complete
            __syncthreads();

            const float* buf = bufs[g % 3];
            const ulonglong2* myrow = (const ulonglong2*)(buf + key*PSTR + half*16);
            const float* wc = w_s + c*DCHUNK + half*16;
            #pragma unroll
            for (int d4 = 0; d4 < 4; d4++) {
                ulonglong2 p = myrow[d4];
                #pragma unroll
                for (int h = 0; h < 8; h++) {
                    ulonglong2 wv = *(const ulonglong2*)(wc + h*D + d4*4);
                    fma2(acc[h], p.x, wv.x);
                    fma2(acc[h], p.y, wv.y);
                }
            }
            __syncthreads();   // reads done before this buffer is refilled (g+3 targets g%3)
        }

        // ----- softmax epilogue; sc_s in buffer just consumed (not an in-flight target) -----
        float* sc_s = bufs[(i*NCHUNK + NCHUNK - 1) % 3];   // 8*392 floats << buffer size
        if (half == 1) {
            #pragma unroll
            for (int h = 0; h < 8; h++) sc_s[h*392 + key] = hsum2(acc[h]);
        }
        __syncthreads();
        float sc[8];
        if (half == 0) {
            #pragma unroll
            for (int h = 0; h < 8; h++) {
                sc[h] = hsum2(acc[h]) + sc_s[h*392 + key] + sc0[h];
                sc_s[h*392 + key] = sc[h];
            }
        }
        __syncthreads();
        int wid = t >> 5, lane = t & 31;
        if (wid < 8) {
            float mx = -1e30f;
            for (int j = lane; j < L; j += 32) mx = fmaxf(mx, sc_s[wid*392 + j]);
            #pragma unroll
            for (int o = 16; o; o >>= 1) mx = fmaxf(mx, __shfl_xor_sync(0xffffffffu, mx, o));
            if (lane == 0) red[wid] = mx;
        }
        __syncthreads();
        float e[8];
        if (half == 0) {
            #pragma unroll
            for (int h = 0; h < 8; h++) { e[h] = __expf(sc[h] - red[h]); sc_s[h*392 + key] = e[h]; }
        }
        __syncthreads();
        if (wid < 8) {
            float s = 0.f;
            for (int j = lane; j < L; j += 32) s += sc_s[wid*392 + j];
            #pragma unroll
            for (int o = 16; o; o >>= 1) s += __shfl_xor_sync(0xffffffffu, s, o);
            if (lane == 0) red[8 + wid] = 1.0f / s;
        }
        __syncthreads();
        if (half == 0) {
            #pragma unroll
            for (int h = 0; h < 8; h++)
                g_score[((size_t)(bq*H + h)*L + q)*L + key] = e[h] * red[8 + h];
        }
        __syncthreads();   // sc_s & w_s free before next m reuses them
    }
}

// ---------------- 4) out = attn @ V  (high-parallelism tiled GEMM) ----------------
#define OQT 16
#define OKT 96
__global__ __launch_bounds__(256) void out_kernel(float* __restrict__ out) {
    __shared__ float at_s[OQT][OKT+4];    // attn tile, rows broadcast-read
    __shared__ float vt_s[DH][OKT+4];     // V transposed: [dh][k]
    int z = blockIdx.x, b = z >> 3, h = z & 7;
    int q0 = blockIdx.y * OQT;
    int t = threadIdx.x, dh = t & 31, qg = t >> 5;   // qg in 0..7, 2 q's each
    unsigned long long acc2[2] = {};
    for (int k0 = 0; k0 < L; k0 += OKT) {
        __syncthreads();
        for (int f = t; f < OQT*(OKT/4); f += 256) {
            int row = f / (OKT/4), c4 = (f % (OKT/4)) * 4;
            *(float4*)&at_s[row][c4] =
                *(const float4*)&g_score[((size_t)z*L + q0 + row)*L + k0 + c4];
        }
        for (int f = t; f < DH*(OKT/4); f += 256) {
            int row = f / (OKT/4), c4 = (f % (OKT/4)) * 4;
            *(float4*)&vt_s[row][c4] =
                *(const float4*)&g_vT[((size_t)z*DH + row)*L + k0 + c4];
        }
        __syncthreads();
        #pragma unroll
        for (int kk = 0; kk < OKT; kk += 4) {
            ulonglong2 v = *(const ulonglong2*)&vt_s[dh][kk];
            #pragma unroll
            for (int i = 0; i < 2; i++) {
                ulonglong2 a = *(const ulonglong2*)&at_s[qg*2 + i][kk];
                fma2(acc2[i], a.x, v.x);
                fma2(acc2[i], a.y, v.y);
            }
        }
    }
    #pragma unroll
    for (int i = 0; i < 2; i++) {
        int q = q0 + qg*2 + i;
        out[(size_t)(b*L + q)*D + h*DH + dh] = hsum2(acc2[i]);
    }
}

// ---------------- launch ----------------
extern "C" void kernel_launch(void* const* d_in, const int* in_sizes, int n_in,
                              void* d_out, int out_size) {
    const float* key      = (const float*)d_in[0];
    const float* query    = (const float*)d_in[1];
    const float* value    = (const float*)d_in[2];
    const float* pos      = (const float*)d_in[3];
    const float* key_mask = (const float*)d_in[4];
    const float* Wk = (const float*)d_in[5];  const float* bk = (const float*)d_in[6];
    const float* Wq = (const float*)d_in[7];  const float* bq = (const float*)d_in[8];
    const float* Wv = (const float*)d_in[9];  const float* bv = (const float*)d_in[10];
    const float* Wr = (const float*)d_in[11]; const float* br = (const float*)d_in[12];
    const float* u  = (const float*)d_in[13]; const float* vp = (const float*)d_in[14];
    float* out = (float*)d_out;

    // 2048 (w) + 3*384*36 (triple buffer) floats = 174080 bytes
    cudaFuncSetAttribute(bd_softmax_kernel, cudaFuncAttributeMaxDynamicSharedMemorySize, 174080);

    proj_kernel<<<dim3(12, 4, 3), 256>>>(key, query, value, Wk, bk, Wq, bq, Wv, bv, u);   // idx 0
    setup_kernel<<<984, 256>>>(key_mask, Wr, vp, br);                                     // idx 1
    vt_kernel<<<16, 256>>>();                                                             // idx 2
    bd_softmax_kernel<<<128, BDT, 174080>>>(pos);                                         // idx 3 (profiled slot)
    out_kernel<<<dim3(16, 24), 256>>>(out);                                               // idx 4
}

// round 10
// speedup vs baseline: 1.0748x; 1.0748x over previous
#include <cuda_runtime.h>

#define BB 2
#define L 384
#define D 256
#define H 8
#define DH 32
#define BL (BB*L)
#define INVS 0.17677669529663687f   // 1/sqrt(32)

// ---------------- scratch (static device globals; no allocations) ----------------
__device__ float g_kproj[BB*H*L*DH];   // [b][h][l][dh]
__device__ float g_qu[BB*H*L*DH];      // (q+u)*INVS, [b][h][l][dh]
__device__ float g_vproj[BB*H*L*DH];   // [b][h][l][dh]
__device__ float g_vT[BB*H*DH*L];      // V transposed: [z][dh][k]
__device__ float g_qlin[BL*D];         // raw q projection [m][d]
__device__ float g_w[BL*H*D];          // folded pos-weights [m][h][d], pre-scaled
__device__ float g_bias[BB*H*L];       // B_D bias term, pre-scaled
__device__ float g_score[BB*H*L*L];    // A_C+bias+mask, then attn  [z][q][k]

// ---------------- helpers ----------------
__device__ __forceinline__ void fma2(unsigned long long& acc, unsigned long long a, unsigned long long b) {
    asm("fma.rn.f32x2 %0, %1, %2, %0;" : "+l"(acc) : "l"(a), "l"(b));
}
__device__ __forceinline__ float hsum2(unsigned long long v) {
    return __uint_as_float((unsigned)v) + __uint_as_float((unsigned)(v >> 32));
}
__device__ __forceinline__ void cp16(unsigned saddr, const void* gptr) {
    asm volatile("cp.async.cg.shared.global [%0], [%1], 16;" :: "r"(saddr), "l"(gptr));
}

// ---------------- 1) QKV projections (transposed smem, scalar acc) ----------------
__global__ __launch_bounds__(256) void proj_kernel(
    const float* __restrict__ key, const float* __restrict__ query, const float* __restrict__ value,
    const float* __restrict__ Wk, const float* __restrict__ bk,
    const float* __restrict__ Wq, const float* __restrict__ bq,
    const float* __restrict__ Wv, const float* __restrict__ bv,
    const float* __restrict__ u)
{
    int op = blockIdx.z;
    const float* X = (op == 0) ? key : (op == 1) ? query : value;
    const float* W = (op == 0) ? Wk  : (op == 1) ? Wq    : Wv;
    const float* bs = (op == 0) ? bk : (op == 1) ? bq    : bv;
    int m0 = blockIdx.x * 64, n0 = blockIdx.y * 64;
    __shared__ float xsT[32][68], wsT[32][68];   // transposed [k][row]
    int t = threadIdx.x, tx = t & 15, ty = t >> 4;
    float c[4][4] = {};
    for (int k0 = 0; k0 < D; k0 += 32) {
        __syncthreads();
        for (int f = t; f < 512; f += 256) {
            int row = f >> 3, c4 = (f & 7) * 4;
            float4 xv = *(const float4*)&X[(m0 + row)*D + k0 + c4];
            float4 wv = *(const float4*)&W[(n0 + row)*D + k0 + c4];
            xsT[c4+0][row] = xv.x; xsT[c4+1][row] = xv.y;
            xsT[c4+2][row] = xv.z; xsT[c4+3][row] = xv.w;
            wsT[c4+0][row] = wv.x; wsT[c4+1][row] = wv.y;
            wsT[c4+2][row] = wv.z; wsT[c4+3][row] = wv.w;
        }
        __syncthreads();
        #pragma unroll
        for (int kk = 0; kk < 32; kk++) {
            float4 a4 = *(const float4*)&xsT[kk][ty*4];
            float4 b4 = *(const float4*)&wsT[kk][tx*4];
            float ar[4] = {a4.x, a4.y, a4.z, a4.w};
            #pragma unroll
            for (int i = 0; i < 4; i++) {
                c[i][0] += ar[i]*b4.x; c[i][1] += ar[i]*b4.y;
                c[i][2] += ar[i]*b4.z; c[i][3] += ar[i]*b4.w;
            }
        }
    }
    int n = n0 + tx*4;                 // 4-aligned; h,dh constant over the float4
    int h = n >> 5, dh = n & 31;
    float4 bs4 = *(const float4*)&bs[n];
    #pragma unroll
    for (int i = 0; i < 4; i++) {
        int m = m0 + ty*4 + i, b = m / L, l = m % L;
        float4 o = {c[i][0]+bs4.x, c[i][1]+bs4.y, c[i][2]+bs4.z, c[i][3]+bs4.w};
        int idx = ((b*H + h)*L + l)*DH + dh;
        if (op == 0)      *(float4*)&g_kproj[idx] = o;
        else if (op == 2) *(float4*)&g_vproj[idx] = o;
        else {
            *(float4*)&g_qlin[m*D + n] = o;
            float4 u4 = *(const float4*)&u[n];
            float4 q = {(o.x+u4.x)*INVS, (o.y+u4.y)*INVS, (o.z+u4.z)*INVS, (o.w+u4.w)*INVS};
            *(float4*)&g_qu[idx] = q;
        }
    }
}

// ---------------- 2) fused setup: ac | w | bias ----------------
__global__ __launch_bounds__(256) void setup_kernel(
    const float* __restrict__ key_mask,
    const float* __restrict__ Wr, const float* __restrict__ vpar,
    const float* __restrict__ br)
{
    __shared__ float sh0[32][68], sh1[32][68];
    int bz = blockIdx.x;
    int t = threadIdx.x, tx = t & 15, ty = t >> 4;

    if (bz < 576) {
        // ---- content scores A_C (+bias +mask) ----
        int idx = bz;
        int z = idx & 15;                 // b*H + h
        int rr = idx >> 4;
        int q0 = (rr % 6) * 64, k0 = (rr / 6) * 64;
        int b = z >> 3;
        for (int f = t; f < 512; f += 256) {
            int row = f >> 3, c4 = (f & 7) * 4;
            float4 qv = *(const float4*)&g_qu[(z*L + q0 + row)*DH + c4];
            float4 kv = *(const float4*)&g_kproj[(z*L + k0 + row)*DH + c4];
            sh0[c4+0][row] = qv.x; sh0[c4+1][row] = qv.y;
            sh0[c4+2][row] = qv.z; sh0[c4+3][row] = qv.w;
            sh1[c4+0][row] = kv.x; sh1[c4+1][row] = kv.y;
            sh1[c4+2][row] = kv.z; sh1[c4+3][row] = kv.w;
        }
        __syncthreads();
        float c[4][4] = {};
        #pragma unroll
        for (int kk = 0; kk < 32; kk++) {
            float4 a4 = *(const float4*)&sh0[kk][ty*4];
            float4 b4 = *(const float4*)&sh1[kk][tx*4];
            float ar[4] = {a4.x, a4.y, a4.z, a4.w};
            #pragma unroll
            for (int i = 0; i < 4; i++) {
                c[i][0] += ar[i]*b4.x; c[i][1] += ar[i]*b4.y;
                c[i][2] += ar[i]*b4.z; c[i][3] += ar[i]*b4.w;
            }
        }
        float msk[4];
        #pragma unroll
        for (int j = 0; j < 4; j++)
            msk[j] = (1.f - key_mask[b*L + k0 + tx*4 + j]) * 1e15f;
        #pragma unroll
        for (int i = 0; i < 4; i++) {
            int q = q0 + ty*4 + i;
            float bias = g_bias[z*L + q];
            float4 o;
            o.x = c[i][0] + bias - msk[0];
            o.y = c[i][1] + bias - msk[1];
            o.z = c[i][2] + bias - msk[2];
            o.w = c[i][3] + bias - msk[3];
            *(float4*)&g_score[((size_t)z*L + q)*L + k0 + tx*4] = o;
        }
    } else if (bz < 960) {
        // ---- w fold: per head h, [768,32] @ Wr_h[32,256] ----
        int idx = bz - 576;
        int h = idx & 7;
        int rr = idx >> 3;
        int m0 = (rr % 12) * 64, n0 = (rr / 12) * 64;
        for (int f = t; f < 512; f += 256) {
            int row = f >> 3, c4 = (f & 7) * 4;
            float4 qv = *(const float4*)&g_qlin[(m0 + row)*D + h*DH + c4];
            float4 vv = *(const float4*)&vpar[h*DH + c4];
            sh0[c4+0][row] = qv.x + vv.x;
            sh0[c4+1][row] = qv.y + vv.y;
            sh0[c4+2][row] = qv.z + vv.z;
            sh0[c4+3][row] = qv.w + vv.w;
        }
        for (int f = t; f < 512; f += 256) {
            int row = f >> 4, c4 = (f & 15) * 4;
            *(float4*)&sh1[row][c4] = *(const float4*)&Wr[(h*DH + row)*D + n0 + c4];
        }
        __syncthreads();
        float c[4][4] = {};
        #pragma unroll
        for (int jj = 0; jj < 32; jj++) {
            float4 a4 = *(const float4*)&sh0[jj][ty*4];
            float4 w4 = *(const float4*)&sh1[jj][tx*4];
            float ar[4] = {a4.x, a4.y, a4.z, a4.w};
            #pragma unroll
            for (int i = 0; i < 4; i++) {
                c[i][0] += ar[i]*w4.x; c[i][1] += ar[i]*w4.y;
                c[i][2] += ar[i]*w4.z; c[i][3] += ar[i]*w4.w;
            }
        }
        #pragma unroll
        for (int i = 0; i < 4; i++) {
            int m = m0 + ty*4 + i;
            float4 o = {c[i][0]*INVS, c[i][1]*INVS, c[i][2]*INVS, c[i][3]*INVS};
            *(float4*)&g_w[(m*H + h)*D + n0 + tx*4] = o;
        }
    } else {
        // ---- B_D bias ----
        int idx = (bz - 960) * 256 + t;
        int m = idx >> 3, h = idx & 7;
        float s = 0.f;
        for (int j = 0; j < DH; j++)
            s += (g_qlin[m*D + h*DH + j] + vpar[h*DH + j]) * br[h*DH + j];
        int b = m / L, l = m % L;
        g_bias[(b*H + h)*L + l] = s * INVS;
    }
}

// ---------------- 2b) V transpose (standalone: keeps bd in profiled launch slot 3) ----------------
__global__ __launch_bounds__(256) void vt_kernel() {
    int z = blockIdx.x;   // 0..15
    for (int f = threadIdx.x; f < L*DH; f += 256) {
        int k = f >> 5, d = f & 31;
        g_vT[((size_t)z*DH + d)*L + k] = g_vproj[((size_t)z*L + k)*DH + d];
    }
}

// ---------------- 3) MAIN: warp-private cp.async pipeline (NO mainloop CTA barriers) ----------------
#define DCHUNK 32
#define PSTR 36          // 32 + 4 pad: stride-36 rows -> conflict-free LDS.128 phases
#define NCHUNK 8         // D / DCHUNK
#define MPB 6            // m's per block; 128 * 6 = 768
#define NG (MPB*NCHUNK)  // 48 chunks per CTA
extern __shared__ float smem3[];
__global__ __launch_bounds__(384, 1) void bd_softmax_kernel(const float* __restrict__ pos) {
    float* w_s = smem3;                        // 2048 floats
    float* bufs[4];
    #pragma unroll
    for (int j = 0; j < 4; j++) bufs[j] = smem3 + 2048 + j*(384*PSTR);   // 13824 floats each
    __shared__ float red[16];
    int t = threadIdx.x;
    int wid = t >> 5, lane = t & 31;
    int m0 = blockIdx.x * MPB;
    unsigned sb[4];
    #pragma unroll
    for (int j = 0; j < 4; j++) sb[j] = (unsigned)__cvta_generic_to_shared(bufs[j]);
    // warp w owns keys/rows 32w..32w+31; loads & reads are warp-private
    int rowbase = wid*32 + (lane >> 3);
    int piece = (lane & 7) << 2;               // word offset within 32-float row

    // prologue: prefetch chunks 0,1 into bufs 0,1 (one group each)
    #pragma unroll
    for (int g = 0; g < 2; g++) {
        const float* src = pos + (size_t)m0*(L*D) + g*DCHUNK;
        #pragma unroll
        for (int p = 0; p < 8; p++) {
            int row = rowbase + p*4;
            cp16(sb[g] + (unsigned)(row*PSTR + piece)*4u, src + row*D + piece);
        }
        asm volatile("cp.async.commit_group;");
    }

    for (int i = 0; i < MPB; i++) {
        int m = m0 + i;
        // w for this m + score row prefetch
        for (int j = t; j < 512; j += 384)
            *(float4*)&w_s[j*4] = *(const float4*)&g_w[(size_t)m*(H*D) + j*4];
        int bq = m / L, q = m - bq*L;
        float sc0[8];
        #pragma unroll
        for (int h = 0; h < 8; h++)
            sc0[h] = g_score[((size_t)(bq*H + h)*L + q)*L + t];
        __syncthreads();   // w_s ready

        unsigned long long acc[8] = {};
        for (int c = 0; c < NCHUNK; c++) {
            int g = i*NCHUNK + c;
            int gp = g + 2;                    // depth-2 prefetch, 4-buffer ring
            if (gp < NG) {
                int mi = gp >> 3, cc = gp & 7;
                const float* src = pos + (size_t)(m0 + mi)*(L*D) + cc*DCHUNK;
                unsigned sd = sb[gp & 3];
                #pragma unroll
                for (int p = 0; p < 8; p++) {
                    int row = rowbase + p*4;
                    cp16(sd + (unsigned)(row*PSTR + piece)*4u, src + row*D + piece);
                }
            }
            asm volatile("cp.async.commit_group;");
            asm volatile("cp.async.wait_group 2;");   // own chunk g complete (warp-private data)
            __syncwarp();

            const ulonglong2* myrow = (const ulonglong2*)(bufs[g & 3] + t*PSTR);
            const float* wc = w_s + c*DCHUNK;
            #pragma unroll
            for (int d4 = 0; d4 < 8; d4++) {
                ulonglong2 p = myrow[d4];
                #pragma unroll
                for (int h = 0; h < 8; h++) {
                    ulonglong2 wv = *(const ulonglong2*)(wc + h*D + d4*4);
                    fma2(acc[h], p.x, wv.x);
                    fma2(acc[h], p.y, wv.y);
                }
            }
            __syncwarp();   // warp-lane reads done before this warp's later refill of same parity
        }

        // ----- softmax epilogue (sc_s = bufs[3]: parity (8i+7)%4, consumed; in-flight = parities 0,1) -----
        __syncthreads();
        float sc[8];
        #pragma unroll
        for (int h = 0; h < 8; h++) sc[h] = hsum2(acc[h]) + sc0[h];
        float* sc_s = bufs[3];   // 8*392 = 3136 floats << 13824
        #pragma unroll
        for (int h = 0; h < 8; h++) sc_s[h*392 + t] = sc[h];
        __syncthreads();
        if (wid < 8) {
            float mx = -1e30f;
            for (int j = lane; j < L; j += 32) mx = fmaxf(mx, sc_s[wid*392 + j]);
            #pragma unroll
            for (int o = 16; o; o >>= 1) mx = fmaxf(mx, __shfl_xor_sync(0xffffffffu, mx, o));
            if (lane == 0) red[wid] = mx;
        }
        __syncthreads();
        float e[8];
        #pragma unroll
        for (int h = 0; h < 8; h++) { e[h] = __expf(sc[h] - red[h]); sc_s[h*392 + t] = e[h]; }
        __syncthreads();
        if (wid < 8) {
            float s = 0.f;
            for (int j = lane; j < L; j += 32) s += sc_s[wid*392 + j];
            #pragma unroll
            for (int o = 16; o; o >>= 1) s += __shfl_xor_sync(0xffffffffu, s, o);
            if (lane == 0) red[8 + wid] = 1.0f / s;
        }
        __syncthreads();
        #pragma unroll
        for (int h = 0; h < 8; h++)
            g_score[((size_t)(bq*H + h)*L + q)*L + t] = e[h] * red[8 + h];
        __syncthreads();   // sc_s reads/writes done before next m's pipeline touches bufs[3]
    }
}

// ---------------- 4) out = attn @ V  (high-parallelism tiled GEMM) ----------------
#define OQT 16
#define OKT 96
__global__ __launch_bounds__(256) void out_kernel(float* __restrict__ out) {
    __shared__ float at_s[OQT][OKT+4];    // attn tile, rows broadcast-read
    __shared__ float vt_s[DH][OKT+4];     // V transposed: [dh][k]
    int z = blockIdx.x, b = z >> 3, h = z & 7;
    int q0 = blockIdx.y * OQT;
    int t = threadIdx.x, dh = t & 31, qg = t >> 5;   // qg in 0..7, 2 q's each
    unsigned long long acc2[2] = {};
    for (int k0 = 0; k0 < L; k0 += OKT) {
        __syncthreads();
        for (int f = t; f < OQT*(OKT/4); f += 256) {
            int row = f / (OKT/4), c4 = (f % (OKT/4)) * 4;
            *(float4*)&at_s[row][c4] =
                *(const float4*)&g_score[((size_t)z*L + q0 + row)*L + k0 + c4];
        }
        for (int f = t; f < DH*(OKT/4); f += 256) {
            int row = f / (OKT/4), c4 = (f % (OKT/4)) * 4;
            *(float4*)&vt_s[row][c4] =
                *(const float4*)&g_vT[((size_t)z*DH + row)*L + k0 + c4];
        }
        __syncthreads();
        #pragma unroll
        for (int kk = 0; kk < OKT; kk += 4) {
            ulonglong2 v = *(const ulonglong2*)&vt_s[dh][kk];
            #pragma unroll
            for (int i = 0; i < 2; i++) {
                ulonglong2 a = *(const ulonglong2*)&at_s[qg*2 + i][kk];
                fma2(acc2[i], a.x, v.x);
                fma2(acc2[i], a.y, v.y);
            }
        }
    }
    #pragma unroll
    for (int i = 0; i < 2; i++) {
        int q = q0 + qg*2 + i;
        out[(size_t)(b*L + q)*D + h*DH + dh] = hsum2(acc2[i]);
    }
}

// ---------------- launch ----------------
extern "C" void kernel_launch(void* const* d_in, const int* in_sizes, int n_in,
                              void* d_out, int out_size) {
    const float* key      = (const float*)d_in[0];
    const float* query    = (const float*)d_in[1];
    const float* value    = (const float*)d_in[2];
    const float* pos      = (const float*)d_in[3];
    const float* key_mask = (const float*)d_in[4];
    const float* Wk = (const float*)d_in[5];  const float* bk = (const float*)d_in[6];
    const float* Wq = (const float*)d_in[7];  const float* bq = (const float*)d_in[8];
    const float* Wv = (const float*)d_in[9];  const float* bv = (const float*)d_in[10];
    const float* Wr = (const float*)d_in[11]; const float* br = (const float*)d_in[12];
    const float* u  = (const float*)d_in[13]; const float* vp = (const float*)d_in[14];
    float* out = (float*)d_out;

    // 2048 (w) + 4*384*36 (quad buffer) floats = 229376 bytes
    cudaFuncSetAttribute(bd_softmax_kernel, cudaFuncAttributeMaxDynamicSharedMemorySize, 229376);

    proj_kernel<<<dim3(12, 4, 3), 256>>>(key, query, value, Wk, bk, Wq, bq, Wv, bv, u);   // idx 0
    setup_kernel<<<984, 256>>>(key_mask, Wr, vp, br);                                     // idx 1
    vt_kernel<<<16, 256>>>();                                                             // idx 2
    bd_softmax_kernel<<<128, 384, 229376>>>(pos);                                         // idx 3 (profiled slot)
    out_kernel<<<dim3(16, 24), 256>>>(out);                                               // idx 4
}